// round 7
// baseline (speedup 1.0000x reference)
#include <cuda_runtime.h>

#define HH 224
#define WW 224
#define NCH 64
#define BB 4

#define TH 32
#define TW 16
#define FC 31            // TW + 15 halo cols
#define ROWSTR 248       // 31*8 floats; 4-row x 8-ch warps hit all 32 banks
#define V2R 34           // V2 rows 6..39  stored at (r-6)
#define V8R 40           // V8 rows 3..42  stored at (r-3)
#define SMEM_BYTES ((V2R + V8R) * ROWSTR * 4)

#define NPART 148        // minmax partial blocks per batch (4x148 = 4 clean waves)

// ---------------- device globals (scratch; no allocation) ----------------
__device__ float g_pmn[BB * NPART];
__device__ float g_pmx[BB * NPART];
__device__ float g_sA[BB];      // 1/(max-min+eps)
__device__ float g_xmin[BB];
__device__ float g_coef[4];     // OLS coefficients c_s
__device__ float g_bnS[NCH];    // folded BN scale
__device__ float g_bnT[NCH];    // folded BN bias

// ---------------- kernel 1: per-sample min/max partials ----------------
__global__ void minmaxK(const float* __restrict__ x) {
    const int b = blockIdx.y;
    const int n4 = HH * WW * NCH / 4;
    const float4* xv = reinterpret_cast<const float4*>(x) + (size_t)b * n4;
    const int stride = gridDim.x * blockDim.x;

    float mn0 = 3.402823466e38f, mx0 = -3.402823466e38f;
    float mn1 = mn0, mx1 = mx0, mn2 = mn0, mx2 = mx0, mn3 = mn0, mx3 = mx0;

    for (int i = blockIdx.x * blockDim.x + threadIdx.x; i < n4; i += 4 * stride) {
        float4 v0 = __ldg(xv + i);
        mn0 = fminf(mn0, fminf(fminf(v0.x, v0.y), fminf(v0.z, v0.w)));
        mx0 = fmaxf(mx0, fmaxf(fmaxf(v0.x, v0.y), fmaxf(v0.z, v0.w)));
        if (i + stride < n4) {
            float4 v1 = __ldg(xv + i + stride);
            mn1 = fminf(mn1, fminf(fminf(v1.x, v1.y), fminf(v1.z, v1.w)));
            mx1 = fmaxf(mx1, fmaxf(fmaxf(v1.x, v1.y), fmaxf(v1.z, v1.w)));
        }
        if (i + 2 * stride < n4) {
            float4 v2 = __ldg(xv + i + 2 * stride);
            mn2 = fminf(mn2, fminf(fminf(v2.x, v2.y), fminf(v2.z, v2.w)));
            mx2 = fmaxf(mx2, fmaxf(fmaxf(v2.x, v2.y), fmaxf(v2.z, v2.w)));
        }
        if (i + 3 * stride < n4) {
            float4 v3 = __ldg(xv + i + 3 * stride);
            mn3 = fminf(mn3, fminf(fminf(v3.x, v3.y), fminf(v3.z, v3.w)));
            mx3 = fmaxf(mx3, fmaxf(fmaxf(v3.x, v3.y), fmaxf(v3.z, v3.w)));
        }
    }
    float mn = fminf(fminf(mn0, mn1), fminf(mn2, mn3));
    float mx = fmaxf(fmaxf(mx0, mx1), fmaxf(mx2, mx3));

    #pragma unroll
    for (int o = 16; o; o >>= 1) {
        mn = fminf(mn, __shfl_xor_sync(0xffffffffu, mn, o));
        mx = fmaxf(mx, __shfl_xor_sync(0xffffffffu, mx, o));
    }
    __shared__ float smn[8], smx[8];
    int lane = threadIdx.x & 31, wid = threadIdx.x >> 5;
    if (lane == 0) { smn[wid] = mn; smx[wid] = mx; }
    __syncthreads();
    if (wid == 0) {
        mn = smn[lane & 7]; mx = smx[lane & 7];
        #pragma unroll
        for (int o = 4; o; o >>= 1) {
            mn = fminf(mn, __shfl_xor_sync(0xffffffffu, mn, o));
            mx = fmaxf(mx, __shfl_xor_sync(0xffffffffu, mx, o));
        }
        if (lane == 0) {
            g_pmn[b * NPART + blockIdx.x] = mn;
            g_pmx[b * NPART + blockIdx.x] = mx;
        }
    }
}

// ---------------- kernel 2: finalize constants (128 threads) ----------------
__global__ void finK(const float* __restrict__ ols,
                     const float* __restrict__ gamma, const float* __restrict__ beta,
                     const float* __restrict__ mean,  const float* __restrict__ var) {
    int t = threadIdx.x;
    int lane = t & 31, w = t >> 5;      // warp w reduces batch w
    {
        float mn = 3.402823466e38f, mx = -3.402823466e38f;
        for (int k = lane; k < NPART; k += 32) {
            mn = fminf(mn, g_pmn[w * NPART + k]);
            mx = fmaxf(mx, g_pmx[w * NPART + k]);
        }
        #pragma unroll
        for (int o = 16; o; o >>= 1) {
            mn = fminf(mn, __shfl_xor_sync(0xffffffffu, mn, o));
            mx = fmaxf(mx, __shfl_xor_sync(0xffffffffu, mx, o));
        }
        if (lane == 0) {
            g_xmin[w] = mn;
            g_sA[w]   = 1.0f / (mx - mn + 1e-6f);
        }
    }
    if (t < NCH) {
        float s = gamma[t] * rsqrtf(var[t] + 1e-3f);
        g_bnS[t] = s;
        g_bnT[t] = beta[t] - mean[t] * s;
    }
    if (t == 0) {
        const float L2 = 0.69314718055994530942f;
        float wv[4], lr[4];
        float wsum = 0.f, wlr = 0.f;
        #pragma unroll
        for (int s = 0; s < 4; s++) {
            wv[s] = ols[s];
            lr[s] = (float)(s + 1) * L2;
            wsum += wv[s];
            wlr  += wv[s] * lr[s];
        }
        float lrbar = wlr / wsum;
        float den = 0.f;
        #pragma unroll
        for (int s = 0; s < 4; s++) {
            float dx = lr[s] - lrbar;
            den += wv[s] * dx * dx;
        }
        #pragma unroll
        for (int s = 0; s < 4; s++) g_coef[s] = wv[s] * (lr[s] - lrbar) / den;
    }
}

// ---------------- register-ring sliding-window scan, single row ----------------
template <int LO, int HI>
__device__ __forceinline__ void scanR(const float* __restrict__ p,
                                      float coef, float* __restrict__ alpha) {
    constexpr int W = LO + HI + 1;
    float ring[W];
    float ws = 0.f;
    #pragma unroll
    for (int k = 0; k < W; k++) { ring[k] = p[(7 - LO + k) * 8]; ws += ring[k]; }
    #pragma unroll
    for (int j = 0; j < TW; j++) {
        alpha[j] += coef * __logf(ws + 1e-6f);
        if (j < TW - 1) {
            float nv = p[(8 + j + HI) * 8];
            ws += nv - ring[j % W];
            ring[j % W] = nv;
        }
    }
}

// dual-row variant: values are pa[col] + pb[col]
template <int LO, int HI>
__device__ __forceinline__ void scanP(const float* __restrict__ pa,
                                      const float* __restrict__ pb,
                                      float coef, float* __restrict__ alpha) {
    constexpr int W = LO + HI + 1;
    float ring[W];
    float ws = 0.f;
    #pragma unroll
    for (int k = 0; k < W; k++) {
        ring[k] = pa[(7 - LO + k) * 8] + pb[(7 - LO + k) * 8];
        ws += ring[k];
    }
    #pragma unroll
    for (int j = 0; j < TW; j++) {
        alpha[j] += coef * __logf(ws + 1e-6f);
        if (j < TW - 1) {
            float nv = pa[(8 + j + HI) * 8] + pb[(8 + j + HI) * 8];
            ws += nv - ring[j % W];
            ring[j % W] = nv;
        }
    }
}

// ---------------- kernel 3: fused main ----------------
__global__ void __launch_bounds__(256, 3)
mainK(const float* __restrict__ x, const float* __restrict__ anchors,
      const float* __restrict__ widths, float* __restrict__ out) {
    extern __shared__ float sm[];
    float* V2 = sm;                        // rows 6..39 at (r-6)
    float* V8 = sm + V2R * ROWSTR;         // rows 3..42 at (r-3)

    const int tid = threadIdx.x;
    const int b  = blockIdx.z;
    const int cg = blockIdx.y;           // channel group of 8
    const int tx = blockIdx.x % (WW / TW), ty = blockIdx.x / (WW / TW);
    const int h0 = ty * TH, w0 = tx * TW;
    const int gc = cg * 8;

    const float sA = g_sA[b];
    const float xmsA = -g_xmin[b] * sA;       // xs = x*sA + xmsA
    const size_t planeB = (size_t)b * HH * WW * NCH;

    // ---- phase 1: column walkers emit V2 and V8 via sliding sums ----
    // 2 halves x 124 float2 col-slots; each walks 31 xs rows.
    {
        const int half = tid >> 7;            // 0 or 1
        const int slot = tid & 127;           // 0..127; <124 active
        if (slot < 124) {
            const int base = half ? 16 : 0;   // first xs tile-row walked
            const int t2lo = half ? 8 : 7,  t2hi = half ? 24 : 23;
            const int t8lo = half ? 11 : 7, t8hi = half ? 30 : 26;
            const int c = slot >> 2;          // spatial col 0..30
            const int q = slot & 3;           // float2 within 8-ch group
            const int gw = w0 - 7 + c;
            const bool wok = (unsigned)gw < (unsigned)WW;
            const float* px = x + planeB + (size_t)gw * NCH + gc + q * 2;
            float* d2 = V2 + slot * 2;
            float* d8 = V8 + slot * 2;

            float2 xsr[8];
            #pragma unroll
            for (int k = 0; k < 8; k++) xsr[k] = make_float2(0.f, 0.f);
            float2 v8s  = make_float2(0.f, 0.f);
            float2 prev = make_float2(0.f, 0.f);

            #pragma unroll
            for (int t = 0; t < 31; t++) {
                int gh = h0 - 7 + base + t;
                float2 cur = make_float2(0.f, 0.f);
                if (wok && (unsigned)gh < (unsigned)HH) {
                    float2 v = *reinterpret_cast<const float2*>(px + (size_t)gh * (WW * NCH));
                    cur = make_float2(fmaf(v.x, sA, xmsA), fmaf(v.y, sA, xmsA));
                }
                // V2 row v = base+t-1 -> slot (v-6)
                if (t >= t2lo && t <= t2hi)
                    *reinterpret_cast<float2*>(d2 + (base + t - 7) * ROWSTR) =
                        make_float2(prev.x + cur.x, prev.y + cur.y);
                // sliding 8-row sum: V8 row v = base+t-4 -> slot (v-3)
                float2 o8 = xsr[t & 7];
                xsr[t & 7] = cur;
                v8s.x += cur.x - o8.x;
                v8s.y += cur.y - o8.y;
                if (t >= t8lo && t <= t8hi)
                    *reinterpret_cast<float2*>(d8 + (base + t - 7) * ROWSTR) = v8s;
                prev = cur;
            }
        }
    }
    __syncthreads();

    float alpha[TW];
    #pragma unroll
    for (int j = 0; j < TW; j++) alpha[j] = 0.f;

    const int ch  = tid & 7;
    const int row = tid >> 3;        // 0..31
    const int R   = 7 + row;
    const float c0 = g_coef[0], c1 = g_coef[1], c2 = g_coef[2], c3 = g_coef[3];

    // ---- phase 2: four scans (single-barrier kernel) ----
    scanR<0, 1>(V2 + (R - 6) * ROWSTR + ch, c0, alpha);
    scanP<1, 2>(V2 + (R - 7) * ROWSTR + ch, V2 + (R - 5) * ROWSTR + ch, c1, alpha);
    scanR<3, 4>(V8 + (R - 3) * ROWSTR + ch, c2, alpha);
    scanP<7, 8>(V8 + (R - 7) * ROWSTR + ch, V8 + (R + 1) * ROWSTR + ch, c3, alpha);

    // ---- per-pixel epilogue: BN -> soft histogram -> sigmoid -> add x ----
    const int gcc = gc + ch;
    float AN[8], W8[8];
    #pragma unroll
    for (int k = 0; k < 8; k++) {
        AN[k] = __ldg(anchors + gcc * 8 + k);
        W8[k] = __ldg(widths  + gcc * 8 + k);
    }
    const float bnS = g_bnS[gcc], bnT = g_bnT[gcc];
    const int gh = h0 + row;
    const size_t base = planeB + ((size_t)gh * WW + w0) * NCH + gcc;

    #pragma unroll
    for (int j = 0; j < TW; j++) {
        float a = fmaf(alpha[j], bnS, bnT);
        float t = 0.f;
        #pragma unroll
        for (int k = 0; k < 8; k++) {
            float d = fabsf(a - AN[k]);
            t += fmaxf(fmaf(-W8[k], d, 1.0f), 0.0f);
        }
        float sig = __fdividef(1.0f, 1.0f + __expf(-t));
        out[base + (size_t)j * NCH] = __ldg(x + base + (size_t)j * NCH) + sig;
    }
}

// ---------------- launch ----------------
extern "C" void kernel_launch(void* const* d_in, const int* in_sizes, int n_in,
                              void* d_out, int out_size) {
    const float* x       = (const float*)d_in[0];
    const float* ols     = (const float*)d_in[1];
    const float* anchors = (const float*)d_in[2];
    const float* widths  = (const float*)d_in[3];
    const float* gamma   = (const float*)d_in[4];
    const float* beta    = (const float*)d_in[5];
    const float* mean    = (const float*)d_in[6];
    const float* var     = (const float*)d_in[7];
    float* out = (float*)d_out;

    cudaFuncSetAttribute(mainK, cudaFuncAttributeMaxDynamicSharedMemorySize, SMEM_BYTES);

    minmaxK<<<dim3(NPART, BB), 256>>>(x);
    finK<<<1, 128>>>(ols, gamma, beta, mean, var);
    mainK<<<dim3((WW / TW) * (HH / TH), 8, BB), 256, SMEM_BYTES>>>(x, anchors, widths, out);
}

// round 9
// speedup vs baseline: 1.0524x; 1.0524x over previous
#include <cuda_runtime.h>

#define HH 224
#define WW 224
#define NCH 64
#define BB 4

#define TH 32
#define TW 16
#define FC 31            // TW + 15 halo cols
#define ROWSTR 248       // 31*8 floats; 4-row x 8-ch warps hit all 32 banks
#define V2R 34           // V2 rows 6..39  stored at (r-6)
#define V8R 40           // V8 rows 3..42  stored at (r-3)
#define SMEM_BYTES ((V2R + V8R) * ROWSTR * 4)

#define NPART 98         // 98*256 threads/batch * 32 float4 = exactly 224*224*64/4

// ---------------- device globals (scratch; no allocation) ----------------
__device__ float g_pmn[BB * NPART];
__device__ float g_pmx[BB * NPART];
__device__ float g_sA[BB];      // 1/(max-min+eps)
__device__ float g_xmin[BB];
__device__ float g_coef[4];     // OLS coefficients c_s
__device__ float g_bnS[NCH];    // folded BN scale
__device__ float g_bnT[NCH];    // folded BN bias

// ---------------- kernel 1: per-sample min/max partials ----------------
// Each thread does exactly 32 grid-strided float4 loads (no bounds checks),
// 8 independent accumulator pairs for MLP.
__global__ void minmaxK(const float* __restrict__ x) {
    const int b = blockIdx.y;
    const int n4 = HH * WW * NCH / 4;
    const float4* xv = reinterpret_cast<const float4*>(x) + (size_t)b * n4;
    const int stride = NPART * 256;
    int i = blockIdx.x * 256 + threadIdx.x;

    float mn[8], mx[8];
    #pragma unroll
    for (int k = 0; k < 8; k++) { mn[k] = 3.402823466e38f; mx[k] = -3.402823466e38f; }

    #pragma unroll
    for (int u = 0; u < 4; u++) {
        #pragma unroll
        for (int k = 0; k < 8; k++) {
            float4 v = __ldg(xv + i + k * stride);
            mn[k] = fminf(mn[k], fminf(fminf(v.x, v.y), fminf(v.z, v.w)));
            mx[k] = fmaxf(mx[k], fmaxf(fmaxf(v.x, v.y), fmaxf(v.z, v.w)));
        }
        i += 8 * stride;
    }
    #pragma unroll
    for (int k = 4; k; k >>= 1)
        #pragma unroll
        for (int j = 0; j < k; j++) {
            mn[j] = fminf(mn[j], mn[j + k]);
            mx[j] = fmaxf(mx[j], mx[j + k]);
        }
    float mnv = mn[0], mxv = mx[0];

    #pragma unroll
    for (int o = 16; o; o >>= 1) {
        mnv = fminf(mnv, __shfl_xor_sync(0xffffffffu, mnv, o));
        mxv = fmaxf(mxv, __shfl_xor_sync(0xffffffffu, mxv, o));
    }
    __shared__ float smn[8], smx[8];
    int lane = threadIdx.x & 31, wid = threadIdx.x >> 5;
    if (lane == 0) { smn[wid] = mnv; smx[wid] = mxv; }
    __syncthreads();
    if (wid == 0) {
        mnv = smn[lane & 7]; mxv = smx[lane & 7];
        #pragma unroll
        for (int o = 4; o; o >>= 1) {
            mnv = fminf(mnv, __shfl_xor_sync(0xffffffffu, mnv, o));
            mxv = fmaxf(mxv, __shfl_xor_sync(0xffffffffu, mxv, o));
        }
        if (lane == 0) {
            g_pmn[b * NPART + blockIdx.x] = mnv;
            g_pmx[b * NPART + blockIdx.x] = mxv;
        }
    }
}

// ---------------- kernel 2: finalize constants (128 threads) ----------------
__global__ void finK(const float* __restrict__ ols,
                     const float* __restrict__ gamma, const float* __restrict__ beta,
                     const float* __restrict__ mean,  const float* __restrict__ var) {
    int t = threadIdx.x;
    int lane = t & 31, w = t >> 5;      // warp w reduces batch w
    {
        float mn = 3.402823466e38f, mx = -3.402823466e38f;
        for (int k = lane; k < NPART; k += 32) {
            mn = fminf(mn, g_pmn[w * NPART + k]);
            mx = fmaxf(mx, g_pmx[w * NPART + k]);
        }
        #pragma unroll
        for (int o = 16; o; o >>= 1) {
            mn = fminf(mn, __shfl_xor_sync(0xffffffffu, mn, o));
            mx = fmaxf(mx, __shfl_xor_sync(0xffffffffu, mx, o));
        }
        if (lane == 0) {
            g_xmin[w] = mn;
            g_sA[w]   = 1.0f / (mx - mn + 1e-6f);
        }
    }
    if (t < NCH) {
        float s = gamma[t] * rsqrtf(var[t] + 1e-3f);
        g_bnS[t] = s;
        g_bnT[t] = beta[t] - mean[t] * s;
    }
    if (t == 0) {
        const float L2 = 0.69314718055994530942f;
        float wv[4], lr[4];
        float wsum = 0.f, wlr = 0.f;
        #pragma unroll
        for (int s = 0; s < 4; s++) {
            wv[s] = ols[s];
            lr[s] = (float)(s + 1) * L2;
            wsum += wv[s];
            wlr  += wv[s] * lr[s];
        }
        float lrbar = wlr / wsum;
        float den = 0.f;
        #pragma unroll
        for (int s = 0; s < 4; s++) {
            float dx = lr[s] - lrbar;
            den += wv[s] * dx * dx;
        }
        #pragma unroll
        for (int s = 0; s < 4; s++) g_coef[s] = wv[s] * (lr[s] - lrbar) / den;
    }
}

// ---------------- register-ring sliding-window scan, single row ----------------
template <int LO, int HI>
__device__ __forceinline__ void scanR(const float* __restrict__ p,
                                      float coef, float* __restrict__ alpha) {
    constexpr int W = LO + HI + 1;
    float ring[W];
    float ws = 0.f;
    #pragma unroll
    for (int k = 0; k < W; k++) { ring[k] = p[(7 - LO + k) * 8]; ws += ring[k]; }
    #pragma unroll
    for (int j = 0; j < TW; j++) {
        alpha[j] += coef * __logf(ws + 1e-6f);
        if (j < TW - 1) {
            float nv = p[(8 + j + HI) * 8];
            ws += nv - ring[j % W];
            ring[j % W] = nv;
        }
    }
}

// dual-row variant: values are pa[col] + pb[col]
template <int LO, int HI>
__device__ __forceinline__ void scanP(const float* __restrict__ pa,
                                      const float* __restrict__ pb,
                                      float coef, float* __restrict__ alpha) {
    constexpr int W = LO + HI + 1;
    float ring[W];
    float ws = 0.f;
    #pragma unroll
    for (int k = 0; k < W; k++) {
        ring[k] = pa[(7 - LO + k) * 8] + pb[(7 - LO + k) * 8];
        ws += ring[k];
    }
    #pragma unroll
    for (int j = 0; j < TW; j++) {
        alpha[j] += coef * __logf(ws + 1e-6f);
        if (j < TW - 1) {
            float nv = pa[(8 + j + HI) * 8] + pb[(8 + j + HI) * 8];
            ws += nv - ring[j % W];
            ring[j % W] = nv;
        }
    }
}

// ---------------- kernel 3: fused main (R6 configuration: 2 CTAs/SM) ----------------
__global__ void __launch_bounds__(256, 2)
mainK(const float* __restrict__ x, const float* __restrict__ anchors,
      const float* __restrict__ widths, float* __restrict__ out) {
    extern __shared__ float sm[];
    float* V2 = sm;                        // rows 6..39 at (r-6)
    float* V8 = sm + V2R * ROWSTR;         // rows 3..42 at (r-3)

    const int tid = threadIdx.x;
    const int b  = blockIdx.z;
    const int cg = blockIdx.y;           // channel group of 8
    const int tx = blockIdx.x % (WW / TW), ty = blockIdx.x / (WW / TW);
    const int h0 = ty * TH, w0 = tx * TW;
    const int gc = cg * 8;

    const float sA = g_sA[b];
    const float xmsA = -g_xmin[b] * sA;       // xs = x*sA + xmsA
    const size_t planeB = (size_t)b * HH * WW * NCH;

    // ---- phase 1: column walkers emit V2 and V8 via sliding sums ----
    {
        const int half = tid >> 7;            // 0 or 1
        const int slot = tid & 127;           // 0..127; <124 active
        if (slot < 124) {
            const int base = half ? 16 : 0;   // first xs tile-row walked
            const int t2lo = half ? 8 : 7,  t2hi = half ? 24 : 23;
            const int t8lo = half ? 11 : 7, t8hi = half ? 30 : 26;
            const int c = slot >> 2;          // spatial col 0..30
            const int q = slot & 3;           // float2 within 8-ch group
            const int gw = w0 - 7 + c;
            const bool wok = (unsigned)gw < (unsigned)WW;
            const float* px = x + planeB + (size_t)gw * NCH + gc + q * 2;
            float* d2 = V2 + slot * 2;
            float* d8 = V8 + slot * 2;

            float2 xsr[8];
            #pragma unroll
            for (int k = 0; k < 8; k++) xsr[k] = make_float2(0.f, 0.f);
            float2 v8s  = make_float2(0.f, 0.f);
            float2 prev = make_float2(0.f, 0.f);

            #pragma unroll
            for (int t = 0; t < 31; t++) {
                int gh = h0 - 7 + base + t;
                float2 cur = make_float2(0.f, 0.f);
                if (wok && (unsigned)gh < (unsigned)HH) {
                    float2 v = *reinterpret_cast<const float2*>(px + (size_t)gh * (WW * NCH));
                    cur = make_float2(fmaf(v.x, sA, xmsA), fmaf(v.y, sA, xmsA));
                }
                if (t >= t2lo && t <= t2hi)
                    *reinterpret_cast<float2*>(d2 + (base + t - 7) * ROWSTR) =
                        make_float2(prev.x + cur.x, prev.y + cur.y);
                float2 o8 = xsr[t & 7];
                xsr[t & 7] = cur;
                v8s.x += cur.x - o8.x;
                v8s.y += cur.y - o8.y;
                if (t >= t8lo && t <= t8hi)
                    *reinterpret_cast<float2*>(d8 + (base + t - 7) * ROWSTR) = v8s;
                prev = cur;
            }
        }
    }
    __syncthreads();

    float alpha[TW];
    #pragma unroll
    for (int j = 0; j < TW; j++) alpha[j] = 0.f;

    const int ch  = tid & 7;
    const int row = tid >> 3;        // 0..31
    const int R   = 7 + row;
    const float c0 = g_coef[0], c1 = g_coef[1], c2 = g_coef[2], c3 = g_coef[3];

    // ---- phase 2: four scans (single-barrier kernel) ----
    scanR<0, 1>(V2 + (R - 6) * ROWSTR + ch, c0, alpha);
    scanP<1, 2>(V2 + (R - 7) * ROWSTR + ch, V2 + (R - 5) * ROWSTR + ch, c1, alpha);
    scanR<3, 4>(V8 + (R - 3) * ROWSTR + ch, c2, alpha);
    scanP<7, 8>(V8 + (R - 7) * ROWSTR + ch, V8 + (R + 1) * ROWSTR + ch, c3, alpha);

    // ---- per-pixel epilogue: BN -> soft histogram -> sigmoid -> add x ----
    const int gcc = gc + ch;
    float AN[8], W8[8];
    #pragma unroll
    for (int k = 0; k < 8; k++) {
        AN[k] = __ldg(anchors + gcc * 8 + k);
        W8[k] = __ldg(widths  + gcc * 8 + k);
    }
    const float bnS = g_bnS[gcc], bnT = g_bnT[gcc];
    const int gh = h0 + row;
    const size_t base = planeB + ((size_t)gh * WW + w0) * NCH + gcc;

    #pragma unroll
    for (int j = 0; j < TW; j++) {
        float a = fmaf(alpha[j], bnS, bnT);
        float t = 0.f;
        #pragma unroll
        for (int k = 0; k < 8; k++) {
            float d = fabsf(a - AN[k]);
            t += fmaxf(fmaf(-W8[k], d, 1.0f), 0.0f);
        }
        float sig = __fdividef(1.0f, 1.0f + __expf(-t));
        out[base + (size_t)j * NCH] = __ldg(x + base + (size_t)j * NCH) + sig;
    }
}

// ---------------- launch ----------------
extern "C" void kernel_launch(void* const* d_in, const int* in_sizes, int n_in,
                              void* d_out, int out_size) {
    const float* x       = (const float*)d_in[0];
    const float* ols     = (const float*)d_in[1];
    const float* anchors = (const float*)d_in[2];
    const float* widths  = (const float*)d_in[3];
    const float* gamma   = (const float*)d_in[4];
    const float* beta    = (const float*)d_in[5];
    const float* mean    = (const float*)d_in[6];
    const float* var     = (const float*)d_in[7];
    float* out = (float*)d_out;

    cudaFuncSetAttribute(mainK, cudaFuncAttributeMaxDynamicSharedMemorySize, SMEM_BYTES);

    minmaxK<<<dim3(NPART, BB), 256>>>(x);
    finK<<<1, 128>>>(ols, gamma, beta, mean, var);
    mainK<<<dim3((WW / TW) * (HH / TH), 8, BB), 256, SMEM_BYTES>>>(x, anchors, widths, out);
}

// round 10
// speedup vs baseline: 1.0715x; 1.0181x over previous
#include <cuda_runtime.h>

#define HH 224
#define WW 224
#define NCH 64
#define BB 4

#define TH 16            // tile rows
#define TW 16            // tile cols
#define FC 31            // TW + 15 halo cols
#define ROWSTR 248       // 31 cols * 8 floats per cg row
#define V2RN 18          // V2 rows 6..23  stored at (r-6)
#define V8RN 24          // V8 rows 3..26  stored at (r-3)
#define CGSTR ((V2RN + V8RN) * ROWSTR + 24)   // 10440 floats; %32==8 -> scans conflict-free
#define SMEM_BYTES (4 * CGSTR * 4)

#define NPART 196        // 196*256 threads/batch * 16 float4 = exactly 224*224*64/4

// ---------------- device globals (scratch; no allocation) ----------------
__device__ float g_pmn[BB * NPART];
__device__ float g_pmx[BB * NPART];
__device__ float g_sA[BB];      // 1/(max-min+eps)
__device__ float g_xmin[BB];
__device__ float g_coef[4];     // OLS coefficients c_s
__device__ float g_bnS[NCH];    // folded BN scale
__device__ float g_bnT[NCH];    // folded BN bias

// ---------------- kernel 1: per-sample min/max partials ----------------
// Each thread: exactly 16 grid-strided float4 loads, 8 independent acc pairs.
__global__ void minmaxK(const float* __restrict__ x) {
    const int b = blockIdx.y;
    const int n4 = HH * WW * NCH / 4;
    const float4* xv = reinterpret_cast<const float4*>(x) + (size_t)b * n4;
    const int stride = NPART * 256;
    int i = blockIdx.x * 256 + threadIdx.x;

    float mn[8], mx[8];
    #pragma unroll
    for (int k = 0; k < 8; k++) { mn[k] = 3.402823466e38f; mx[k] = -3.402823466e38f; }

    #pragma unroll
    for (int u = 0; u < 2; u++) {
        #pragma unroll
        for (int k = 0; k < 8; k++) {
            float4 v = __ldg(xv + i + k * stride);
            mn[k] = fminf(mn[k], fminf(fminf(v.x, v.y), fminf(v.z, v.w)));
            mx[k] = fmaxf(mx[k], fmaxf(fmaxf(v.x, v.y), fmaxf(v.z, v.w)));
        }
        i += 8 * stride;
    }
    #pragma unroll
    for (int k = 4; k; k >>= 1)
        #pragma unroll
        for (int j = 0; j < k; j++) {
            mn[j] = fminf(mn[j], mn[j + k]);
            mx[j] = fmaxf(mx[j], mx[j + k]);
        }
    float mnv = mn[0], mxv = mx[0];

    #pragma unroll
    for (int o = 16; o; o >>= 1) {
        mnv = fminf(mnv, __shfl_xor_sync(0xffffffffu, mnv, o));
        mxv = fmaxf(mxv, __shfl_xor_sync(0xffffffffu, mxv, o));
    }
    __shared__ float smn[8], smx[8];
    int lane = threadIdx.x & 31, wid = threadIdx.x >> 5;
    if (lane == 0) { smn[wid] = mnv; smx[wid] = mxv; }
    __syncthreads();
    if (wid == 0) {
        mnv = smn[lane & 7]; mxv = smx[lane & 7];
        #pragma unroll
        for (int o = 4; o; o >>= 1) {
            mnv = fminf(mnv, __shfl_xor_sync(0xffffffffu, mnv, o));
            mxv = fmaxf(mxv, __shfl_xor_sync(0xffffffffu, mxv, o));
        }
        if (lane == 0) {
            g_pmn[b * NPART + blockIdx.x] = mnv;
            g_pmx[b * NPART + blockIdx.x] = mxv;
        }
    }
}

// ---------------- kernel 2: finalize constants (128 threads) ----------------
__global__ void finK(const float* __restrict__ ols,
                     const float* __restrict__ gamma, const float* __restrict__ beta,
                     const float* __restrict__ mean,  const float* __restrict__ var) {
    int t = threadIdx.x;
    int lane = t & 31, w = t >> 5;      // warp w reduces batch w
    {
        float mn = 3.402823466e38f, mx = -3.402823466e38f;
        for (int k = lane; k < NPART; k += 32) {
            mn = fminf(mn, g_pmn[w * NPART + k]);
            mx = fmaxf(mx, g_pmx[w * NPART + k]);
        }
        #pragma unroll
        for (int o = 16; o; o >>= 1) {
            mn = fminf(mn, __shfl_xor_sync(0xffffffffu, mn, o));
            mx = fmaxf(mx, __shfl_xor_sync(0xffffffffu, mx, o));
        }
        if (lane == 0) {
            g_xmin[w] = mn;
            g_sA[w]   = 1.0f / (mx - mn + 1e-6f);
        }
    }
    if (t < NCH) {
        float s = gamma[t] * rsqrtf(var[t] + 1e-3f);
        g_bnS[t] = s;
        g_bnT[t] = beta[t] - mean[t] * s;
    }
    if (t == 0) {
        const float L2 = 0.69314718055994530942f;
        float wv[4], lr[4];
        float wsum = 0.f, wlr = 0.f;
        #pragma unroll
        for (int s = 0; s < 4; s++) {
            wv[s] = ols[s];
            lr[s] = (float)(s + 1) * L2;
            wsum += wv[s];
            wlr  += wv[s] * lr[s];
        }
        float lrbar = wlr / wsum;
        float den = 0.f;
        #pragma unroll
        for (int s = 0; s < 4; s++) {
            float dx = lr[s] - lrbar;
            den += wv[s] * dx * dx;
        }
        #pragma unroll
        for (int s = 0; s < 4; s++) g_coef[s] = wv[s] * (lr[s] - lrbar) / den;
    }
}

// ---------------- register-ring sliding-window scan, single row ----------------
template <int LO, int HI>
__device__ __forceinline__ void scanR(const float* __restrict__ p,
                                      float coef, float* __restrict__ alpha) {
    constexpr int W = LO + HI + 1;
    float ring[W];
    float ws = 0.f;
    #pragma unroll
    for (int k = 0; k < W; k++) { ring[k] = p[(7 - LO + k) * 8]; ws += ring[k]; }
    #pragma unroll
    for (int j = 0; j < TW; j++) {
        alpha[j] += coef * __logf(ws + 1e-6f);
        if (j < TW - 1) {
            float nv = p[(8 + j + HI) * 8];
            ws += nv - ring[j % W];
            ring[j % W] = nv;
        }
    }
}

// dual-row variant: values are pa[col] + pb[col]
template <int LO, int HI>
__device__ __forceinline__ void scanP(const float* __restrict__ pa,
                                      const float* __restrict__ pb,
                                      float coef, float* __restrict__ alpha) {
    constexpr int W = LO + HI + 1;
    float ring[W];
    float ws = 0.f;
    #pragma unroll
    for (int k = 0; k < W; k++) {
        ring[k] = pa[(7 - LO + k) * 8] + pb[(7 - LO + k) * 8];
        ws += ring[k];
    }
    #pragma unroll
    for (int j = 0; j < TW; j++) {
        alpha[j] += coef * __logf(ws + 1e-6f);
        if (j < TW - 1) {
            float nv = pa[(8 + j + HI) * 8] + pb[(8 + j + HI) * 8];
            ws += nv - ring[j % W];
            ring[j % W] = nv;
        }
    }
}

// ---------------- kernel 3: fused main (512 thr, 32 channels/CTA) ----------------
__global__ void __launch_bounds__(512, 1)
mainK(const float* __restrict__ x, const float* __restrict__ anchors,
      const float* __restrict__ widths, float* __restrict__ out) {
    extern __shared__ float sm[];   // 4 cg buffers: [V2 18 rows | V8 24 rows | pad]

    const int tid = threadIdx.x;
    const int b   = blockIdx.z;
    const int gcB = blockIdx.y * 32;     // channel base: 0 or 32 (128B-aligned line)
    const int tx = blockIdx.x % (WW / TW), ty = blockIdx.x / (WW / TW);
    const int h0 = ty * TH, w0 = tx * TW;

    const float sA = g_sA[b];
    const float xmsA = -g_xmin[b] * sA;  // xs = x*sA + xmsA
    const size_t planeB = (size_t)b * HH * WW * NCH;

    // ---- phase 1: column walkers emit V2 and V8 (float4 = 4ch, full lines) ----
    if (tid < 496) {
        const int half = tid >= 248;
        const int slot = half ? tid - 248 : tid;   // 0..247
        const int c = slot >> 3;                   // spatial col 0..30
        const int q = slot & 7;                    // float4 index in 32 ch
        const int cg = q >> 1, hp = q & 1;
        const int base = half ? 12 : 0;            // first xs tile-row walked
        const int t2lo = half ? 19 : 7,  t2hi = half ? 24 : 18;
        const int t8lo = half ? 19 : 7,  t8hi = half ? 30 : 18;
        const int gw = w0 - 7 + c;
        const bool wok = (unsigned)gw < (unsigned)WW;
        const float* px = x + planeB + (size_t)gw * NCH + gcB + q * 4;
        float* d2 = sm + cg * CGSTR + c * 8 + hp * 4;
        float* d8 = d2 + V2RN * ROWSTR;

        float4 xsr[8];
        #pragma unroll
        for (int k = 0; k < 8; k++) xsr[k] = make_float4(0.f, 0.f, 0.f, 0.f);
        float4 v8s  = make_float4(0.f, 0.f, 0.f, 0.f);
        float4 prev = make_float4(0.f, 0.f, 0.f, 0.f);

        #pragma unroll
        for (int tt = 0; tt < 19; tt++) {
            int t = base + tt;
            int gh = h0 - 7 + t;
            float4 cur = make_float4(0.f, 0.f, 0.f, 0.f);
            if (wok && (unsigned)gh < (unsigned)HH) {
                float4 v = *reinterpret_cast<const float4*>(px + (size_t)gh * (WW * NCH));
                cur = make_float4(fmaf(v.x, sA, xmsA), fmaf(v.y, sA, xmsA),
                                  fmaf(v.z, sA, xmsA), fmaf(v.w, sA, xmsA));
            }
            // V2 row v=t-1 -> slot (v-6) = t-7
            if (t >= t2lo && t <= t2hi)
                *reinterpret_cast<float4*>(d2 + (t - 7) * ROWSTR) =
                    make_float4(prev.x + cur.x, prev.y + cur.y,
                                prev.z + cur.z, prev.w + cur.w);
            // sliding 8-row sum -> V8 row e=t-4 -> slot (e-3) = t-7
            float4 o8 = xsr[tt & 7];
            xsr[tt & 7] = cur;
            v8s.x += cur.x - o8.x; v8s.y += cur.y - o8.y;
            v8s.z += cur.z - o8.z; v8s.w += cur.w - o8.w;
            if (t >= t8lo && t <= t8hi)
                *reinterpret_cast<float4*>(d8 + (t - 7) * ROWSTR) = v8s;
            prev = cur;
        }
    }
    __syncthreads();

    float alpha[TW];
    #pragma unroll
    for (int j = 0; j < TW; j++) alpha[j] = 0.f;

    // ---- phase 2: scans; thread = (row 0..15, ch 0..31) ----
    const int ch  = tid & 31;
    const int row = tid >> 5;        // 0..15
    const int R   = 7 + row;
    const float* V2 = sm + (ch >> 3) * CGSTR + (ch & 7);
    const float* V8 = V2 + V2RN * ROWSTR;
    const float c0 = g_coef[0], c1 = g_coef[1], c2 = g_coef[2], c3 = g_coef[3];

    scanR<0, 1>(V2 + (R - 6) * ROWSTR, c0, alpha);
    scanP<1, 2>(V2 + (R - 7) * ROWSTR, V2 + (R - 5) * ROWSTR, c1, alpha);
    scanR<3, 4>(V8 + (R - 3) * ROWSTR, c2, alpha);
    scanP<7, 8>(V8 + (R - 7) * ROWSTR, V8 + (R + 1) * ROWSTR, c3, alpha);

    // ---- per-pixel epilogue: BN -> soft histogram -> sigmoid -> add x ----
    const int gcc = gcB + ch;
    float AN[8], W8[8];
    #pragma unroll
    for (int k = 0; k < 8; k++) {
        AN[k] = __ldg(anchors + gcc * 8 + k);
        W8[k] = __ldg(widths  + gcc * 8 + k);
    }
    const float bnS = g_bnS[gcc], bnT = g_bnT[gcc];
    const int gh = h0 + row;
    const size_t base = planeB + ((size_t)gh * WW + w0) * NCH + gcc;

    #pragma unroll
    for (int j = 0; j < TW; j++) {
        float a = fmaf(alpha[j], bnS, bnT);
        float t = 0.f;
        #pragma unroll
        for (int k = 0; k < 8; k++) {
            float d = fabsf(a - AN[k]);
            t += fmaxf(fmaf(-W8[k], d, 1.0f), 0.0f);
        }
        float sig = __fdividef(1.0f, 1.0f + __expf(-t));
        out[base + (size_t)j * NCH] = __ldg(x + base + (size_t)j * NCH) + sig;
    }
}

// ---------------- launch ----------------
extern "C" void kernel_launch(void* const* d_in, const int* in_sizes, int n_in,
                              void* d_out, int out_size) {
    const float* x       = (const float*)d_in[0];
    const float* ols     = (const float*)d_in[1];
    const float* anchors = (const float*)d_in[2];
    const float* widths  = (const float*)d_in[3];
    const float* gamma   = (const float*)d_in[4];
    const float* beta    = (const float*)d_in[5];
    const float* mean    = (const float*)d_in[6];
    const float* var     = (const float*)d_in[7];
    float* out = (float*)d_out;

    cudaFuncSetAttribute(mainK, cudaFuncAttributeMaxDynamicSharedMemorySize, SMEM_BYTES);

    minmaxK<<<dim3(NPART, BB), 256>>>(x);
    finK<<<1, 128>>>(ols, gamma, beta, mean, var);
    mainK<<<dim3((WW / TW) * (HH / TH), 2, BB), 512, SMEM_BYTES>>>(x, anchors, widths, out);
}

// round 11
// speedup vs baseline: 1.1424x; 1.0662x over previous
#include <cuda_runtime.h>

#define HH 224
#define WW 224
#define NCH 64
#define BB 4

#define TH 16            // tile rows
#define TWT 32           // tile cols (2 scan halves of 16)
#define TW 16            // cols per scan thread
#define FCC 47           // TWT + 15 halo cols
#define ROWSTR 376       // 47*8 floats; %32==24 -> 4-row x 8-ch warps conflict-free
#define V2RN 18          // V2 rows 6..23 stored at (r-6)
#define V8RN 24          // V8 rows 3..26 stored at (r-3)
#define SMEM_BYTES ((V2RN + V8RN) * ROWSTR * 4)

#define NPART 196        // 196*256 threads/batch * 16 float4 = exactly 224*224*64/4

// ---------------- device globals (scratch; no allocation) ----------------
__device__ float g_pmn[BB * NPART];
__device__ float g_pmx[BB * NPART];
__device__ float g_sA[BB];      // 1/(max-min+eps)
__device__ float g_xmin[BB];
__device__ float g_coef[4];     // OLS coefficients c_s
__device__ float g_bnS[NCH];    // folded BN scale
__device__ float g_bnT[NCH];    // folded BN bias

// ---------------- kernel 1: per-sample min/max partials ----------------
__global__ void minmaxK(const float* __restrict__ x) {
    const int b = blockIdx.y;
    const float4* xv = reinterpret_cast<const float4*>(x) + (size_t)b * (HH * WW * NCH / 4);
    const int stride = NPART * 256;
    int i = blockIdx.x * 256 + threadIdx.x;

    float mn[8], mx[8];
    #pragma unroll
    for (int k = 0; k < 8; k++) { mn[k] = 3.402823466e38f; mx[k] = -3.402823466e38f; }

    #pragma unroll
    for (int u = 0; u < 2; u++) {
        #pragma unroll
        for (int k = 0; k < 8; k++) {
            float4 v = __ldg(xv + i + k * stride);
            mn[k] = fminf(mn[k], fminf(fminf(v.x, v.y), fminf(v.z, v.w)));
            mx[k] = fmaxf(mx[k], fmaxf(fmaxf(v.x, v.y), fmaxf(v.z, v.w)));
        }
        i += 8 * stride;
    }
    #pragma unroll
    for (int k = 4; k; k >>= 1)
        #pragma unroll
        for (int j = 0; j < k; j++) {
            mn[j] = fminf(mn[j], mn[j + k]);
            mx[j] = fmaxf(mx[j], mx[j + k]);
        }
    float mnv = mn[0], mxv = mx[0];

    #pragma unroll
    for (int o = 16; o; o >>= 1) {
        mnv = fminf(mnv, __shfl_xor_sync(0xffffffffu, mnv, o));
        mxv = fmaxf(mxv, __shfl_xor_sync(0xffffffffu, mxv, o));
    }
    __shared__ float smn[8], smx[8];
    int lane = threadIdx.x & 31, wid = threadIdx.x >> 5;
    if (lane == 0) { smn[wid] = mnv; smx[wid] = mxv; }
    __syncthreads();
    if (wid == 0) {
        mnv = smn[lane & 7]; mxv = smx[lane & 7];
        #pragma unroll
        for (int o = 4; o; o >>= 1) {
            mnv = fminf(mnv, __shfl_xor_sync(0xffffffffu, mnv, o));
            mxv = fmaxf(mxv, __shfl_xor_sync(0xffffffffu, mxv, o));
        }
        if (lane == 0) {
            g_pmn[b * NPART + blockIdx.x] = mnv;
            g_pmx[b * NPART + blockIdx.x] = mxv;
        }
    }
}

// ---------------- kernel 2: finalize constants (128 threads) ----------------
__global__ void finK(const float* __restrict__ ols,
                     const float* __restrict__ gamma, const float* __restrict__ beta,
                     const float* __restrict__ mean,  const float* __restrict__ var) {
    int t = threadIdx.x;
    int lane = t & 31, w = t >> 5;      // warp w reduces batch w
    {
        float mn = 3.402823466e38f, mx = -3.402823466e38f;
        for (int k = lane; k < NPART; k += 32) {
            mn = fminf(mn, g_pmn[w * NPART + k]);
            mx = fmaxf(mx, g_pmx[w * NPART + k]);
        }
        #pragma unroll
        for (int o = 16; o; o >>= 1) {
            mn = fminf(mn, __shfl_xor_sync(0xffffffffu, mn, o));
            mx = fmaxf(mx, __shfl_xor_sync(0xffffffffu, mx, o));
        }
        if (lane == 0) {
            g_xmin[w] = mn;
            g_sA[w]   = 1.0f / (mx - mn + 1e-6f);
        }
    }
    if (t < NCH) {
        float s = gamma[t] * rsqrtf(var[t] + 1e-3f);
        g_bnS[t] = s;
        g_bnT[t] = beta[t] - mean[t] * s;
    }
    if (t == 0) {
        const float L2 = 0.69314718055994530942f;
        float wv[4], lr[4];
        float wsum = 0.f, wlr = 0.f;
        #pragma unroll
        for (int s = 0; s < 4; s++) {
            wv[s] = ols[s];
            lr[s] = (float)(s + 1) * L2;
            wsum += wv[s];
            wlr  += wv[s] * lr[s];
        }
        float lrbar = wlr / wsum;
        float den = 0.f;
        #pragma unroll
        for (int s = 0; s < 4; s++) {
            float dx = lr[s] - lrbar;
            den += wv[s] * dx * dx;
        }
        #pragma unroll
        for (int s = 0; s < 4; s++) g_coef[s] = wv[s] * (lr[s] - lrbar) / den;
    }
}

// ---------------- register-ring sliding-window scan, single row ----------------
template <int LO, int HI>
__device__ __forceinline__ void scanR(const float* __restrict__ p,
                                      float coef, float* __restrict__ alpha) {
    constexpr int W = LO + HI + 1;
    float ring[W];
    float ws = 0.f;
    #pragma unroll
    for (int k = 0; k < W; k++) { ring[k] = p[(7 - LO + k) * 8]; ws += ring[k]; }
    #pragma unroll
    for (int j = 0; j < TW; j++) {
        alpha[j] += coef * __logf(ws + 1e-6f);
        if (j < TW - 1) {
            float nv = p[(8 + j + HI) * 8];
            ws += nv - ring[j % W];
            ring[j % W] = nv;
        }
    }
}

// dual-row variant: values are pa[col] + pb[col]
template <int LO, int HI>
__device__ __forceinline__ void scanP(const float* __restrict__ pa,
                                      const float* __restrict__ pb,
                                      float coef, float* __restrict__ alpha) {
    constexpr int W = LO + HI + 1;
    float ring[W];
    float ws = 0.f;
    #pragma unroll
    for (int k = 0; k < W; k++) {
        ring[k] = pa[(7 - LO + k) * 8] + pb[(7 - LO + k) * 8];
        ws += ring[k];
    }
    #pragma unroll
    for (int j = 0; j < TW; j++) {
        alpha[j] += coef * __logf(ws + 1e-6f);
        if (j < TW - 1) {
            float nv = pa[(8 + j + HI) * 8] + pb[(8 + j + HI) * 8];
            ws += nv - ring[j % W];
            ring[j % W] = nv;
        }
    }
}

// ---------------- kernel 3: fused main (256 thr, 3 CTAs/SM = 24 warps) ----------------
__global__ void __launch_bounds__(256, 3)
mainK(const float* __restrict__ x, const float* __restrict__ anchors,
      const float* __restrict__ widths, float* __restrict__ out) {
    extern __shared__ float sm[];
    float* V2 = sm;                        // rows 6..23 at (r-6)
    float* V8 = sm + V2RN * ROWSTR;        // rows 3..26 at (r-3)

    const int tid = threadIdx.x;
    const int b  = blockIdx.z;
    const int cg = blockIdx.y;             // channel group of 8
    const int tx = blockIdx.x % (WW / TWT), ty = blockIdx.x / (WW / TWT);
    const int h0 = ty * TH, w0 = tx * TWT;
    const int gc = cg * 8;

    const float sA = g_sA[b];
    const float xmsA = -g_xmin[b] * sA;    // xs = x*sA + xmsA
    const size_t planeB = (size_t)b * HH * WW * NCH;

    // ---- phase 1: column walkers emit V2 and V8 via sliding sums ----
    // 188 walkers = 94 float4 col-slots x 2 row-halves; 19 xs rows each.
    if (tid < 188) {
        const int half = tid >= 94;
        const int slot = half ? tid - 94 : tid;   // 0..93
        const int c = slot >> 1;                  // spatial col 0..46
        const int q = slot & 1;                   // float4 half of 8ch
        const int base = half ? 12 : 0;           // first xs tile-row walked
        const int t2lo = half ? 19 : 7,  t2hi = half ? 24 : 18;
        const int t8lo = half ? 19 : 7,  t8hi = half ? 30 : 18;
        const int gw = w0 - 7 + c;
        const bool wok = (unsigned)gw < (unsigned)WW;
        const float* px = x + planeB + (size_t)gw * NCH + gc + q * 4;
        float* d2 = V2 + c * 8 + q * 4;
        float* d8 = V8 + c * 8 + q * 4;

        float4 xsr[8];
        #pragma unroll
        for (int k = 0; k < 8; k++) xsr[k] = make_float4(0.f, 0.f, 0.f, 0.f);
        float4 v8s  = make_float4(0.f, 0.f, 0.f, 0.f);
        float4 prev = make_float4(0.f, 0.f, 0.f, 0.f);

        #pragma unroll
        for (int tt = 0; tt < 19; tt++) {
            int t = base + tt;
            int gh = h0 - 7 + t;
            float4 cur = make_float4(0.f, 0.f, 0.f, 0.f);
            if (wok && (unsigned)gh < (unsigned)HH) {
                float4 v = *reinterpret_cast<const float4*>(px + (size_t)gh * (WW * NCH));
                cur = make_float4(fmaf(v.x, sA, xmsA), fmaf(v.y, sA, xmsA),
                                  fmaf(v.z, sA, xmsA), fmaf(v.w, sA, xmsA));
            }
            // V2 row v=t-1 -> slot v-6 = t-7
            if (t >= t2lo && t <= t2hi)
                *reinterpret_cast<float4*>(d2 + (t - 7) * ROWSTR) =
                    make_float4(prev.x + cur.x, prev.y + cur.y,
                                prev.z + cur.z, prev.w + cur.w);
            // sliding 8-row sum -> V8 row e=t-4 -> slot e-3 = t-7
            float4 o8 = xsr[tt & 7];
            xsr[tt & 7] = cur;
            v8s.x += cur.x - o8.x; v8s.y += cur.y - o8.y;
            v8s.z += cur.z - o8.z; v8s.w += cur.w - o8.w;
            if (t >= t8lo && t <= t8hi)
                *reinterpret_cast<float4*>(d8 + (t - 7) * ROWSTR) = v8s;
            prev = cur;
        }
    }
    __syncthreads();

    float alpha[TW];
    #pragma unroll
    for (int j = 0; j < TW; j++) alpha[j] = 0.f;

    // ---- phase 2: scans; thread = (colhalf, row, ch); warp = 4 rows x 8 ch ----
    const int ch    = tid & 7;
    const int row   = (tid >> 3) & 15;     // 0..15
    const int halfc = tid >> 7;            // 0 or 1: cols 0..15 / 16..31
    const int R     = 7 + row;
    const int cofs  = halfc * 16 * 8;      // +16 cols for half 1
    const float* p2 = V2 + (R - 6) * ROWSTR + cofs + ch;
    const float* p8 = V8 + (R - 3) * ROWSTR + cofs + ch;
    const float c0 = g_coef[0], c1 = g_coef[1], c2 = g_coef[2], c3 = g_coef[3];

    scanR<0, 1>(p2, c0, alpha);
    scanP<1, 2>(p2 - ROWSTR, p2 + ROWSTR, c1, alpha);
    scanR<3, 4>(p8, c2, alpha);
    scanP<7, 8>(p8 - 4 * ROWSTR, p8 + 4 * ROWSTR, c3, alpha);

    // ---- per-pixel epilogue: BN -> soft histogram -> sigmoid -> add x ----
    const int gcc = gc + ch;
    float AN[8], W8[8];
    #pragma unroll
    for (int k = 0; k < 8; k++) {
        AN[k] = __ldg(anchors + gcc * 8 + k);
        W8[k] = __ldg(widths  + gcc * 8 + k);
    }
    const float bnS = g_bnS[gcc], bnT = g_bnT[gcc];
    const int gh = h0 + row;
    const size_t base = planeB + ((size_t)gh * WW + w0 + halfc * 16) * NCH + gcc;

    #pragma unroll
    for (int j = 0; j < TW; j++) {
        float a = fmaf(alpha[j], bnS, bnT);
        float t = 0.f;
        #pragma unroll
        for (int k = 0; k < 8; k++) {
            float d = fabsf(a - AN[k]);
            t += fmaxf(fmaf(-W8[k], d, 1.0f), 0.0f);
        }
        float sig = __fdividef(1.0f, 1.0f + __expf(-t));
        out[base + (size_t)j * NCH] = __ldg(x + base + (size_t)j * NCH) + sig;
    }
}

// ---------------- launch ----------------
extern "C" void kernel_launch(void* const* d_in, const int* in_sizes, int n_in,
                              void* d_out, int out_size) {
    const float* x       = (const float*)d_in[0];
    const float* ols     = (const float*)d_in[1];
    const float* anchors = (const float*)d_in[2];
    const float* widths  = (const float*)d_in[3];
    const float* gamma   = (const float*)d_in[4];
    const float* beta    = (const float*)d_in[5];
    const float* mean    = (const float*)d_in[6];
    const float* var     = (const float*)d_in[7];
    float* out = (float*)d_out;

    cudaFuncSetAttribute(mainK, cudaFuncAttributeMaxDynamicSharedMemorySize, SMEM_BYTES);

    minmaxK<<<dim3(NPART, BB), 256>>>(x);
    finK<<<1, 128>>>(ols, gamma, beta, mean, var);
    mainK<<<dim3((WW / TWT) * (HH / TH), 8, BB), 256, SMEM_BYTES>>>(x, anchors, widths, out);
}